// round 17
// baseline (speedup 1.0000x reference)
#include <cuda_runtime.h>
#include <cuda_fp16.h>
#include <mma.h>
#include <math.h>
#include <cstdint>

using namespace nvcuda;
typedef __half hf;

#define C    8
#define L    512
#define NCF  (1024*8*2048)     // 16,777,216
#define LL   (512*512)

// ---- fp16 scratch: A-side tensors hi+lo, B-side hi only ----
__device__ hf g_c0[NCF], g_c1[NCF], g_c2[NCF];       // conv outs (B-side)
__device__ hf g_qh[NCF], g_ql[NCF];                  // q (A-side in qk)
__device__ hf g_k[NCF];                              // k (B-side)
__device__ hf g_v[NCF];                              // v (B-side)
__device__ hf g_a[NCF];                              // attn out (B-side in olin)
__device__ hf g_ph[128*LL], g_pl[128*LL];            // P hi/lo (A-side in pv)
__device__ hf g_wh[4*C*65536], g_wl[4*C*65536];      // weights (A-side)
__device__ float g_rsum[65536];

// ---- helpers ----
__device__ __forceinline__ uint32_t s2u(const void* p) {
    return (uint32_t)__cvta_generic_to_shared(p);
}
__device__ __forceinline__ void cpa16(uint32_t s, const void* g) {
    asm volatile("cp.async.cg.shared.global [%0], [%1], 16;" :: "r"(s), "l"(g));
}
#define CPCOMMIT() asm volatile("cp.async.commit_group;" ::: "memory")
#define CPWAIT()   asm volatile("cp.async.wait_group 0;" ::: "memory")

__device__ __forceinline__ void hsplit(float x, hf& h, hf& l) {
    h = __float2half_rn(x);
    l = __float2half_rn(x - __half2float(h));
}
__device__ __forceinline__ uint32_t packh2(hf a, hf b) {
    __half2 t = __halves2half2(a, b);
    return *(uint32_t*)&t;
}
__device__ __forceinline__ void pack8hl(const float* v, uint4& H, uint4& Lo) {
    hf h[8], l[8];
    #pragma unroll
    for (int i = 0; i < 8; i++) hsplit(v[i], h[i], l[i]);
    H  = make_uint4(packh2(h[0],h[1]), packh2(h[2],h[3]), packh2(h[4],h[5]), packh2(h[6],h[7]));
    Lo = make_uint4(packh2(l[0],l[1]), packh2(l[2],l[3]), packh2(l[4],l[5]), packh2(l[6],l[7]));
}
__device__ __forceinline__ void pack8h(const float* v, uint4& H) {
    hf h[8];
    #pragma unroll
    for (int i = 0; i < 8; i++) h[i] = __float2half_rn(v[i]);
    H = make_uint4(packh2(h[0],h[1]), packh2(h[2],h[3]), packh2(h[4],h[5]), packh2(h[6],h[7]));
}

typedef wmma::fragment<wmma::accumulator, 16, 16, 16, float> AccFrag;

// GEMM warp grid 4x2 (wm: 32-row tiles, wn: 64-col tiles), acc[2][4].
// K-chunk = 64 (4 ks steps), 2 smem stages.
// stage layouts (bytes):
//  qk  (55296): Qh 0  Ql 18432  K 36864     [K-major 128x72 hf, ldm 72]
//  qkv (54272): Wh 0  Wl 18432  AT 36864    [A 128x72 ldm 72; AT 64x136 ldm 136]
//  pv  (54272): Ph 0  Pl 18432  V 36864     [V 64x136 ldm 136]

// A (hi/lo) row_major K-major ldm 72; B single col_major K-major ldm 72
__device__ __forceinline__ void mma2_rAcB(const char* buf, int wm, int wn, AccFrag (&acc)[2][4]) {
    const hf* Ah = (const hf*)(buf);
    const hf* Al = (const hf*)(buf + 18432);
    const hf* B  = (const hf*)(buf + 36864);
    #pragma unroll
    for (int ks = 0; ks < 4; ks++) {
        wmma::fragment<wmma::matrix_b, 16, 16, 16, hf, wmma::col_major> bf[4];
        #pragma unroll
        for (int j = 0; j < 4; j++)
            wmma::load_matrix_sync(bf[j], B + (wn * 64 + j * 16) * 72 + ks * 16, 72);
        #pragma unroll
        for (int i = 0; i < 2; i++) {
            int m_off = wm * 32 + i * 16;
            wmma::fragment<wmma::matrix_a, 16, 16, 16, hf, wmma::row_major> ah, al;
            wmma::load_matrix_sync(ah, Ah + m_off * 72 + ks * 16, 72);
            wmma::load_matrix_sync(al, Al + m_off * 72 + ks * 16, 72);
            #pragma unroll
            for (int j = 0; j < 4; j++) {
                wmma::mma_sync(acc[i][j], ah, bf[j], acc[i][j]);
                wmma::mma_sync(acc[i][j], al, bf[j], acc[i][j]);
            }
        }
    }
}

// A (hi/lo) row_major K-major ldm 72; B single row_major [k][n] ldm 136
__device__ __forceinline__ void mma2_rArB(const char* buf, int wm, int wn, AccFrag (&acc)[2][4]) {
    const hf* Ah = (const hf*)(buf);
    const hf* Al = (const hf*)(buf + 18432);
    const hf* B  = (const hf*)(buf + 36864);
    #pragma unroll
    for (int ks = 0; ks < 4; ks++) {
        wmma::fragment<wmma::matrix_b, 16, 16, 16, hf, wmma::row_major> bf[4];
        #pragma unroll
        for (int j = 0; j < 4; j++)
            wmma::load_matrix_sync(bf[j], B + (ks * 16) * 136 + wn * 64 + j * 16, 136);
        #pragma unroll
        for (int i = 0; i < 2; i++) {
            int m_off = wm * 32 + i * 16;
            wmma::fragment<wmma::matrix_a, 16, 16, 16, hf, wmma::row_major> ah, al;
            wmma::load_matrix_sync(ah, Ah + m_off * 72 + ks * 16, 72);
            wmma::load_matrix_sync(al, Al + m_off * 72 + ks * 16, 72);
            #pragma unroll
            for (int j = 0; j < 4; j++) {
                wmma::mma_sync(acc[i][j], ah, bf[j], acc[i][j]);
                wmma::mma_sync(acc[i][j], al, bf[j], acc[i][j]);
            }
        }
    }
}

#define DECL_ACC() \
    AccFrag acc[2][4]; \
    _Pragma("unroll") for (int i_ = 0; i_ < 2; i_++) \
        _Pragma("unroll") for (int j_ = 0; j_ < 4; j_++) wmma::fill_fragment(acc[i_][j_], 0.0f);

#define EPI_TO_CS() \
    __syncthreads(); \
    { float* Cs_ = (float*)smem; \
      _Pragma("unroll") for (int i_ = 0; i_ < 2; i_++) \
        _Pragma("unroll") for (int j_ = 0; j_ < 4; j_++) \
          wmma::store_matrix_sync(Cs_ + (wm*32 + i_*16)*132 + wn*64 + j_*16, acc[i_][j_], 132, wmma::mem_row_major); } \
    __syncthreads();

// ============================================================
// conv_tc: tensor-core 3x3 conv via im2col, fused with prep_w.
// grid (2048, 8): bx<1024 -> conv (n, 32-row y-tile); bx>=1024 -> prep.
// GEMM per CTA: M=256 (yl,w), K=72->80 (tap*8+ci), N=24->32 (proj*8+co).
// A = x hi/lo fp16 (ldm 88), B = conv weights single fp16 (ldm 40).
// smem: Ah 0(45056) Al 45056 B 90112(6400) xt 96512(10880) = 107392.
// ============================================================
#define CONV_SMEM 107392
__global__ void __launch_bounds__(256, 2)
conv_tc(const float* __restrict__ x,
        const float* __restrict__ cwq, const float* __restrict__ cwk,
        const float* __restrict__ cwv,
        const float* __restrict__ lwq, const float* __restrict__ lwk,
        const float* __restrict__ lwv, const float* __restrict__ lwo) {
    extern __shared__ __align__(16) char smem[];
    const int tid = threadIdx.x;

    if (blockIdx.x >= 1024) {
        int idx = ((blockIdx.x - 1024) * 8 + blockIdx.y) * 256 + tid;  // 0..2M-1
        if (idx < 65536) g_rsum[idx] = 0.0f;
        int t = idx >> 19, off = idx & 524287;
        const float* src = (t == 0) ? lwq : (t == 1) ? lwk : (t == 2) ? lwv : lwo;
        hf h, l;
        hsplit(src[off], h, l);
        g_wh[idx] = h; g_wl[idx] = l;
        return;
    }

    hf* Ah = (hf*)smem;
    hf* Al = (hf*)(smem + 45056);
    hf* Bm = (hf*)(smem + 90112);
    float* xt = (float*)(smem + 96512);    // [8 ci][34 yy][10 xx]
    const int n = blockIdx.x, y0 = blockIdx.y * 32;
    const int b = n >> 9, l = n & 511;

    // zero B (pad rows/cols must be exact zeros) + load x tile with halo
    for (int i = tid; i < 1600; i += 256) ((uint32_t*)Bm)[i] = 0u;
    for (int i = tid; i < 2720; i += 256) {
        int ci = i / 340, rem = i % 340;
        int yy = rem / 10, xx = rem % 10;
        int y = y0 + yy - 1, xc = xx - 1;
        float v = 0.f;
        if (y >= 0 && y < 256 && xc >= 0 && xc < 8)
            v = x[(((size_t)(b*8 + ci)*512 + l)*256 + y)*8 + xc];
        xt[i] = v;
    }
    __syncthreads();

    // fill B[k=tap*8+ci][n=proj*8+co] and build im2col A (one row per thread)
    for (int i = tid; i < 1728; i += 256) {
        int proj = i / 576, r = i % 576;
        int co = r / 72, k = r % 72;
        int tap = k >> 3, ci = k & 7;
        const float* cw = (proj == 0) ? cwq : (proj == 1) ? cwk : cwv;
        Bm[(tap*8 + ci)*40 + proj*8 + co] = __float2half_rn(cw[(co*8 + ci)*9 + tap]);
    }
    {
        const int yl = tid >> 3, w = tid & 7;
        hf* arow = Ah + tid * 88;
        hf* lrow = Al + tid * 88;
        #pragma unroll
        for (int tap = 0; tap < 9; tap++) {
            const int ky = tap / 3, kx = tap % 3;
            hf h8[8], l8[8];
            #pragma unroll
            for (int ci = 0; ci < 8; ci++)
                hsplit(xt[ci*340 + (yl + ky)*10 + (w + kx)], h8[ci], l8[ci]);
            *(uint4*)(arow + tap*8) = make_uint4(packh2(h8[0],h8[1]), packh2(h8[2],h8[3]),
                                                 packh2(h8[4],h8[5]), packh2(h8[6],h8[7]));
            *(uint4*)(lrow + tap*8) = make_uint4(packh2(l8[0],l8[1]), packh2(l8[2],l8[3]),
                                                 packh2(l8[4],l8[5]), packh2(l8[6],l8[7]));
        }
        *(uint4*)(arow + 72) = make_uint4(0,0,0,0);   // zero K-pad 72..79
        *(uint4*)(lrow + 72) = make_uint4(0,0,0,0);
    }
    __syncthreads();

    // MMA: each warp 32 rows x 32 cols; 5 k-steps x 2 splits
    const int wid = tid >> 5;
    wmma::fragment<wmma::accumulator, 16, 16, 16, float> cacc[2][2];
    #pragma unroll
    for (int i = 0; i < 2; i++)
        #pragma unroll
        for (int j = 0; j < 2; j++) wmma::fill_fragment(cacc[i][j], 0.0f);
    #pragma unroll
    for (int ks = 0; ks < 5; ks++) {
        wmma::fragment<wmma::matrix_b, 16, 16, 16, hf, wmma::row_major> bf[2];
        #pragma unroll
        for (int j = 0; j < 2; j++)
            wmma::load_matrix_sync(bf[j], Bm + (ks*16)*40 + j*16, 40);
        #pragma unroll
        for (int i = 0; i < 2; i++) {
            int m = wid * 32 + i * 16;
            wmma::fragment<wmma::matrix_a, 16, 16, 16, hf, wmma::row_major> ah, al;
            wmma::load_matrix_sync(ah, Ah + m*88 + ks*16, 88);
            wmma::load_matrix_sync(al, Al + m*88 + ks*16, 88);
            #pragma unroll
            for (int j = 0; j < 2; j++) {
                wmma::mma_sync(cacc[i][j], ah, bf[j], cacc[i][j]);
                wmma::mma_sync(cacc[i][j], al, bf[j], cacc[i][j]);
            }
        }
    }
    __syncthreads();            // all warps done reading Ah/Al
    float* Cs = (float*)smem;   // 256 x 44 f32, aliases Ah
    #pragma unroll
    for (int i = 0; i < 2; i++)
        #pragma unroll
        for (int j = 0; j < 2; j++)
            wmma::store_matrix_sync(Cs + (wid*32 + i*16)*44 + j*16, cacc[i][j], 44, wmma::mem_row_major);
    __syncthreads();

    // scatter: col co of proj -> g_cP[n*16384 + co*2048 + y0*8 + r] (r contiguous)
    if (tid < 128) {
        #pragma unroll 4
        for (int col = 0; col < 24; col++) {
            int proj = col >> 3, co = col & 7;
            hf* dst = ((proj == 0) ? g_c0 : (proj == 1) ? g_c1 : g_c2)
                      + (size_t)n*16384 + co*2048 + y0*8;
            hf va = __float2half_rn(Cs[(2*tid)   * 44 + col]);
            hf vb = __float2half_rn(Cs[(2*tid+1) * 44 + col]);
            *(uint32_t*)(dst + 2*tid) = packh2(va, vb);
        }
    }
}

// ============================================================
// qkv_wm: transposed proj. K=64 chunks, 2-stage. RoPE fused.
// grid (64, 2, 24), block 256, 2 CTAs/SM.
// ============================================================
#define QKV_SMEM 108544
__global__ void __launch_bounds__(256, 2)
qkv_wm() {
    extern __shared__ __align__(16) char smem[];
    const uint32_t sb = s2u(smem);
    const int tid = threadIdx.x, wid = tid >> 5;
    const int wm = wid >> 1, wn = wid & 1;
    const int c = blockIdx.z & 7, proj = blockIdx.z >> 3;
    const int m0 = blockIdx.x * 128, g0 = blockIdx.y * 128, n0 = m0 >> 3;
    const hf* Ac  = (proj == 0) ? g_c0 : (proj == 1) ? g_c1 : g_c2;
    const hf* Wh_g = g_wh + (size_t)proj * 524288;
    const hf* Wl_g = g_wl + (size_t)proj * 524288;

    DECL_ACC();

    #define QKVLD(s, kc) { \
        uint32_t sbase = sb + (s) * 54272; int k0 = (kc) * 64; \
        _Pragma("unroll") for (int i = 0; i < 4; i++) { \
            int ch = tid + i * 256; \
            int gr = ch >> 3, c8 = ch & 7; \
            size_t gb = (size_t)c * 65536 + (size_t)(g0 + gr) * 256 + k0 + c8 * 8; \
            cpa16(sbase + gr * 144 + c8 * 16,         Wh_g + gb); \
            cpa16(sbase + 18432 + gr * 144 + c8 * 16, Wl_g + gb); \
            int hr = ch & 63, nl = ch >> 6; \
            size_t ga = (size_t)(n0 + nl) * 16384 + c * 2048 + (size_t)(k0 + hr) * 8; \
            cpa16(sbase + 36864 + hr * 272 + nl * 16, Ac + ga); \
        } }

    QKVLD(0, 0); CPCOMMIT();
    for (int kc = 0; kc < 4; kc++) {
        CPWAIT(); __syncthreads();
        if (kc < 3) { QKVLD((kc + 1) & 1, kc + 1); CPCOMMIT(); }
        mma2_rArB(smem + (kc & 1) * 54272, wm, wn, acc);
    }

    EPI_TO_CS();
    const float* Cs = (const float*)smem;
    #pragma unroll
    for (int it = 0; it < 8; it++) {
        int p = tid + it * 256;
        int nl = p >> 7, gr = p & 127;
        const float* src = Cs + gr * 132 + nl * 8;
        float4 v01 = *(const float4*)(src);
        float4 v23 = *(const float4*)(src + 4);
        float v[8] = {v01.x, v01.y, v01.z, v01.w, v23.x, v23.y, v23.z, v23.w};
        int g = g0 + gr;
        if (proj < 2 && (g & 31) < 4) {        // fused RoPE
            int l = (n0 + nl) & 511;
            int jb = (g & 31) * 4;
            #pragma unroll
            for (int t = 0; t < 4; t++) {
                float invf = exp2f(-(float)(jb + t) * (13.287712379549449f / 16.0f));
                float sn, cn;
                sincosf((float)l * invf, &sn, &cn);
                float a = v[2*t], bq = v[2*t+1];
                v[2*t]   = a * cn - bq * sn;
                v[2*t+1] = bq * cn + a * sn;
            }
        }
        size_t e = (size_t)(n0 + nl) * 16384 + (size_t)c * 2048 + (size_t)g * 8;
        if (proj == 0) {
            uint4 H, Lo;
            pack8hl(v, H, Lo);
            *(uint4*)(g_qh + e) = H;
            *(uint4*)(g_ql + e) = Lo;
        } else {
            uint4 H;
            pack8h(v, H);
            *(uint4*)(((proj == 1) ? g_k : g_v) + e) = H;
        }
    }
}

// ============================================================
// qk_wm: K=64 chunks, 2-stage. Epilogue: qk f32 + P hi/lo + sums.
// grid (4, 4, 128), block 256, 2 CTAs/SM.
// ============================================================
#define QK_SMEM 110592
__global__ void __launch_bounds__(256, 2)
qk_wm(const float* __restrict__ prev, float* __restrict__ qk) {
    extern __shared__ __align__(16) char smem[];
    const uint32_t sb = s2u(smem);
    const int tid = threadIdx.x, wid = tid >> 5;
    const int wm = wid >> 1, wn = wid & 1;
    const int z = blockIdx.z;
    const int b = z >> 6, c = (z >> 3) & 7, nh = z & 7;
    const int l0 = blockIdx.y * 128, m0 = blockIdx.x * 128;
    const size_t coff = (size_t)c * 2048 + nh * 256;
    const size_t bL = (size_t)b * 512;

    DECL_ACC();

    #define QKLD(s, kc) { \
        uint32_t sbase = sb + (s) * 55296; int k0 = (kc) * 64; \
        _Pragma("unroll") for (int i = 0; i < 4; i++) { \
            int ch = tid + i * 256; \
            int r = ch >> 3, c8 = ch & 7; \
            uint32_t so = r * 144 + c8 * 16; \
            size_t ga = (bL + l0 + r) * 16384 + coff + k0 + c8 * 8; \
            size_t gb = (bL + m0 + r) * 16384 + coff + k0 + c8 * 8; \
            cpa16(sbase + so,         g_qh + ga); \
            cpa16(sbase + 18432 + so, g_ql + ga); \
            cpa16(sbase + 36864 + so, g_k + gb); \
        } }

    QKLD(0, 0); CPCOMMIT();
    for (int kc = 0; kc < 4; kc++) {
        CPWAIT(); __syncthreads();
        if (kc < 3) { QKLD((kc + 1) & 1, kc + 1); CPCOMMIT(); }
        mma2_rAcB(smem + (kc & 1) * 55296, wm, wn, acc);
    }

    EPI_TO_CS();
    const float* Cs = (const float*)smem;
    const int col4 = (tid & 31) * 4;
    const int rb = tid >> 5;
    const int lane = tid & 31;
    #pragma unroll 4
    for (int jj = 0; jj < 16; jj++) {
        int r = rb + jj * 8;
        float4 cv = *(const float4*)(Cs + r * 132 + col4);
        size_t idx = (size_t)z * LL + (size_t)(l0 + r) * 512 + m0 + col4;
        float4 pv = *(const float4*)(prev + idx);
        float4 o;
        o.x = cv.x * 0.0625f + pv.x;
        o.y = cv.y * 0.0625f + pv.y;
        o.z = cv.z * 0.0625f + pv.z;
        o.w = cv.w * 0.0625f + pv.w;
        *(float4*)(qk + idx) = o;
        float e0 = __expf(o.x), e1 = __expf(o.y);
        float e2 = __expf(o.z), e3 = __expf(o.w);
        hf h0, lo0, h1, lo1, h2, lo2, h3, lo3;
        hsplit(e0, h0, lo0); hsplit(e1, h1, lo1);
        hsplit(e2, h2, lo2); hsplit(e3, h3, lo3);
        *(uint2*)(g_ph + idx) = make_uint2(packh2(h0, h1), packh2(h2, h3));
        *(uint2*)(g_pl + idx) = make_uint2(packh2(lo0, lo1), packh2(lo2, lo3));
        float s = e0 + e1 + e2 + e3;
        #pragma unroll
        for (int off = 16; off; off >>= 1) s += __shfl_xor_sync(~0u, s, off);
        if (lane == 0) atomicAdd(&g_rsum[z * 512 + l0 + r], s);
    }
}

// ============================================================
// pv_wm: K=64 chunks (8), 2-stage. A = P hi/lo, B = V single.
// grid (2, 4, 128), block 256, 2 CTAs/SM.
// ============================================================
#define PV_SMEM 109056
__global__ void __launch_bounds__(256, 2)
pv_wm() {
    extern __shared__ __align__(16) char smem[];
    const uint32_t sb = s2u(smem);
    const int tid = threadIdx.x, wid = tid >> 5;
    const int wm = wid >> 1, wn = wid & 1;
    const int z = blockIdx.z;
    const int b = z >> 6, c = (z >> 3) & 7, nh = z & 7;
    const int l0 = blockIdx.y * 128, d0 = blockIdx.x * 128;
    const size_t coff = (size_t)c * 2048 + nh * 256;
    const size_t bL = (size_t)b * 512;
    float* rinv = (float*)(smem + 108544);
    if (tid < 128) rinv[tid] = 1.0f / g_rsum[z * 512 + l0 + tid];

    DECL_ACC();

    #define PVLD(s, kc) { \
        uint32_t sbase = sb + (s) * 54272; int k0 = (kc) * 64; \
        _Pragma("unroll") for (int i = 0; i < 4; i++) { \
            int ch = tid + i * 256; \
            int r = ch >> 3, c8 = ch & 7; \
            size_t gp = (size_t)z * LL + (size_t)(l0 + r) * 512 + k0 + c8 * 8; \
            cpa16(sbase + r * 144 + c8 * 16,         g_ph + gp); \
            cpa16(sbase + 18432 + r * 144 + c8 * 16, g_pl + gp); \
            int mr = ch >> 4, d8 = ch & 15; \
            size_t gv = (bL + k0 + mr) * 16384 + coff + d0 + d8 * 8; \
            cpa16(sbase + 36864 + mr * 272 + d8 * 16, g_v + gv); \
        } }

    PVLD(0, 0); CPCOMMIT();
    for (int kc = 0; kc < 8; kc++) {
        CPWAIT(); __syncthreads();
        if (kc < 7) { PVLD((kc + 1) & 1, kc + 1); CPCOMMIT(); }
        mma2_rArB(smem + (kc & 1) * 54272, wm, wn, acc);
    }

    EPI_TO_CS();
    const float* Cs = (const float*)smem;
    #pragma unroll
    for (int it = 0; it < 8; it++) {
        int r = (tid >> 4) + it * 16;
        int col8 = (tid & 15) * 8;
        float4 a1 = *(const float4*)(Cs + r * 132 + col8);
        float4 a2 = *(const float4*)(Cs + r * 132 + col8 + 4);
        float iv = rinv[r];
        float v[8] = {a1.x*iv, a1.y*iv, a1.z*iv, a1.w*iv, a2.x*iv, a2.y*iv, a2.z*iv, a2.w*iv};
        uint4 H;
        pack8h(v, H);
        size_t e = (bL + l0 + r) * 16384 + coff + d0 + col8;
        *(uint4*)(g_a + e) = H;
    }
}

// ============================================================
// olin_wm: wo proj, K=64 chunks, 2-stage. -> f32 out.
// grid (64, 2, 8), block 256, 2 CTAs/SM.
// ============================================================
__global__ void __launch_bounds__(256, 2)
olin_wm(float* __restrict__ out) {
    extern __shared__ __align__(16) char smem[];
    const uint32_t sb = s2u(smem);
    const int tid = threadIdx.x, wid = tid >> 5;
    const int wm = wid >> 1, wn = wid & 1;
    const int c = blockIdx.z, m0 = blockIdx.x * 128, g0 = blockIdx.y * 128, n0 = m0 >> 3;
    const hf* Wh_g = g_wh + (size_t)3 * 524288;
    const hf* Wl_g = g_wl + (size_t)3 * 524288;

    DECL_ACC();

    #define OLD(s, kc) { \
        uint32_t sbase = sb + (s) * 54272; int k0 = (kc) * 64; \
        _Pragma("unroll") for (int i = 0; i < 4; i++) { \
            int ch = tid + i * 256; \
            int gr = ch >> 3, c8 = ch & 7; \
            size_t gb = (size_t)c * 65536 + (size_t)(g0 + gr) * 256 + k0 + c8 * 8; \
            cpa16(sbase + gr * 144 + c8 * 16,         Wh_g + gb); \
            cpa16(sbase + 18432 + gr * 144 + c8 * 16, Wl_g + gb); \
            int hr = ch & 63, nl = ch >> 6; \
            size_t ga = (size_t)(n0 + nl) * 16384 + c * 2048 + (size_t)(k0 + hr) * 8; \
            cpa16(sbase + 36864 + hr * 272 + nl * 16, g_a + ga); \
        } }

    OLD(0, 0); CPCOMMIT();
    for (int kc = 0; kc < 4; kc++) {
        CPWAIT(); __syncthreads();
        if (kc < 3) { OLD((kc + 1) & 1, kc + 1); CPCOMMIT(); }
        mma2_rArB(smem + (kc & 1) * 54272, wm, wn, acc);
    }

    EPI_TO_CS();
    const float* Cs = (const float*)smem;
    #pragma unroll
    for (int it = 0; it < 8; it++) {
        int p = tid + it * 256;
        int nl = p >> 7, gr = p & 127;
        int n = n0 + nl, bb = n >> 9, l = n & 511;
        float4 o1 = *(const float4*)(Cs + gr * 132 + nl * 8);
        float4 o2 = *(const float4*)(Cs + gr * 132 + nl * 8 + 4);
        size_t e = ((size_t)(bb * 8 + c) * 512 + l) * 2048 + (size_t)(g0 + gr) * 8;
        *(float4*)(out + e)     = o1;
        *(float4*)(out + e + 4) = o2;
    }
}

// ============================================================
extern "C" void kernel_launch(void* const* d_in, const int* in_sizes, int n_in,
                              void* d_out, int out_size) {
    const float* x    = (const float*)d_in[0];
    const float* prev = (const float*)d_in[1];
    const float* cw_q = (const float*)d_in[2];
    const float* cw_k = (const float*)d_in[3];
    const float* cw_v = (const float*)d_in[4];
    const float* wq   = (const float*)d_in[5];
    const float* wk   = (const float*)d_in[6];
    const float* wv   = (const float*)d_in[7];
    const float* wo   = (const float*)d_in[8];
    float* out    = (float*)d_out;
    float* qk_out = out + (size_t)NCF;

    cudaFuncSetAttribute(conv_tc, cudaFuncAttributeMaxDynamicSharedMemorySize, CONV_SMEM);
    cudaFuncSetAttribute(qkv_wm,  cudaFuncAttributeMaxDynamicSharedMemorySize, QKV_SMEM);
    cudaFuncSetAttribute(olin_wm, cudaFuncAttributeMaxDynamicSharedMemorySize, QKV_SMEM);
    cudaFuncSetAttribute(qk_wm,   cudaFuncAttributeMaxDynamicSharedMemorySize, QK_SMEM);
    cudaFuncSetAttribute(pv_wm,   cudaFuncAttributeMaxDynamicSharedMemorySize, PV_SMEM);

    conv_tc<<<dim3(2048, 8), 256, CONV_SMEM>>>(x, cw_q, cw_k, cw_v, wq, wk, wv, wo);
    qkv_wm<<<dim3(64, 2, 24), 256, QKV_SMEM>>>();
    qk_wm<<<dim3(4, 4, 128), 256, QK_SMEM>>>(prev, qk_out);
    pv_wm<<<dim3(2, 4, 128), 256, PV_SMEM>>>();
    olin_wm<<<dim3(64, 2, 8), 256, QKV_SMEM>>>(out);
}